// round 13
// baseline (speedup 1.0000x reference)
#include <cuda_runtime.h>
#include <cstdint>

// Problem constants
#define T_STEPS 2048
#define BATCH   256
#define IN_DIM  64
#define HID     256

// Tiling: 16 row-groups x 8 j-CTAs = 128 CTAs, 256 threads each.
#define GROUPS   16
#define JCTAS    8
#define ROWS     16
#define JW       32

// Device scratch
__device__ float g_hs[(size_t)T_STEPS * BATCH * HID];   // h trajectory [T][B][H] (also the exchange buffer)
__device__ unsigned int g_cnt[GROUPS * 64];             // per-producer counters at [grp*64 + jc*8]
__device__ unsigned int g_done[GROUPS * 32];            // per-group completion counters at [grp*32]

typedef unsigned long long ull;

// ---- packed fp32x2 helpers ----
__device__ __forceinline__ void fma2(ull& acc, ull a, ull b) {
    asm("fma.rn.f32x2 %0, %1, %2, %0;" : "+l"(acc) : "l"(a), "l"(b));
}
__device__ __forceinline__ float redpair(ull v) {
    float lo = __uint_as_float((unsigned int)(v & 0xffffffffULL));
    float hi = __uint_as_float((unsigned int)(v >> 32));
    return lo + hi;
}
__device__ __forceinline__ ull packf(float lo, float hi) {
    return (ull)__float_as_uint(lo) | ((ull)__float_as_uint(hi) << 32);
}
__device__ __forceinline__ float fast_sig(float x) {
    return __fdividef(1.f, 1.f + __expf(-x));
}
__device__ __forceinline__ float fast_tanh(float x) {
    float y;
    asm("tanh.approx.f32 %0, %1;" : "=f"(y) : "f"(x));
    return y;
}
__device__ __forceinline__ unsigned int ld_acq(const unsigned int* p) {
    unsigned int v;
    asm volatile("ld.acquire.gpu.global.u32 %0, [%1];" : "=r"(v) : "l"(p));
    return v;
}
__device__ __forceinline__ void red_release(unsigned int* p) {
    asm volatile("red.release.gpu.global.add.u32 [%0], %1;" :: "l"(p), "r"(1u) : "memory");
}
__device__ __forceinline__ uint32_t smem_u32(const void* p) {
    uint32_t a;
    asm("{ .reg .u64 t; cvta.to.shared.u64 t, %1; cvt.u32.u64 %0, t; }" : "=r"(a) : "l"(p));
    return a;
}
__device__ __forceinline__ void cp_async16(uint32_t saddr, const void* gaddr) {
    asm volatile("cp.async.cg.shared.global [%0], [%1], 16;" :: "r"(saddr), "l"(gaddr) : "memory");
}
__device__ __forceinline__ void cp_async_commit_wait() {
    asm volatile("cp.async.commit_group;" ::: "memory");
    asm volatile("cp.async.wait_group 0;" ::: "memory");
}

// Per-warp reduction scratch: [8 warps][4 jw][72 floats]
#define RED_WSTRIDE 288
#define RED_JSTRIDE 72

// =====================================================================
// Persistent recurrent kernel: register-resident weights,
// tournament reduction, per-producer counters + incremental slice fetch.
// =====================================================================
__global__ void __launch_bounds__(256, 1) k_rec(
    const float* __restrict__ input,   // [T][B][I]
    const float* __restrict__ hidden,  // [1][B][3]
    const float* __restrict__ W_dec,   // [H][3]
    const float* __restrict__ b_dec,   // [H]
    const float* __restrict__ W_ih,    // [3H][I]
    const float* __restrict__ W_hh,    // [3H][H]
    const float* __restrict__ b_ih,    // [3H]
    const float* __restrict__ b_hh)    // [3H]
{
    __shared__ float h_s[ROWS * HID];            // 16 KB, XOR-swizzled (16B-chunk)
    __shared__ float x_s[ROWS * IN_DIM];         // 4 KB
    __shared__ float red_s[8 * RED_WSTRIDE];     // 9 KB per-warp gate scratch

    const int tid = threadIdx.x;
    const int lane = tid & 31;
    const int warp = tid >> 5;
    const int kslice = lane & 7;          // k in [kslice*32, kslice*32+32)
    const int jw = lane >> 3;             // j within warp (0..3)
    const int jloc = warp * 4 + jw;       // 0..31
    const int grp = blockIdx.x >> 3;      // row group
    const int jc = blockIdx.x & 7;
    const int rbase = grp * ROWS;
    const int jg = jc * JW + jloc;        // global hidden column

    unsigned int* grp_cnt = &g_cnt[grp * 64];      // 8 producer counters, stride 8
    unsigned int* my_cnt  = grp_cnt + jc * 8;
    const uint32_t hs_base = smem_u32(h_s);

    // swizzled float offset of column jg within an h_s row
    const int jsw = (((jg >> 2) ^ ((jg >> 5) & 7)) << 2) + (jg & 3);

    const bool bit2 = (kslice & 4) != 0;
    const bool bit1 = (kslice & 2) != 0;
    const bool bit0 = (kslice & 1) != 0;
    float* red_w = red_s + warp * RED_WSTRIDE + jw * RED_JSTRIDE;
    const int red_store_ofs = (kslice >> 2) * 4 + (kslice & 3);

    // staging geometry: warp stages rows 2w,2w+1; lanes<16: row = 2w+(lane>>3), col-chunk = lane&7 within slice
    const int srow = 2 * warp + ((lane >> 3) & 1);
    const int scol = lane & 7;

    // --- load weights into registers (packed f32x2) ---
    ull whr[16], whz[16], whn[16];
    ull wxr[4],  wxz[4],  wxn[4];
    {
        const float4* W4 = (const float4*)W_hh;   // row stride 64 float4
        #pragma unroll
        for (int c = 0; c < 8; c++) {
            float4 vr = __ldg(&W4[((size_t)(0 * HID + jg)) * 64 + kslice * 8 + c]);
            float4 vz = __ldg(&W4[((size_t)(1 * HID + jg)) * 64 + kslice * 8 + c]);
            float4 vn = __ldg(&W4[((size_t)(2 * HID + jg)) * 64 + kslice * 8 + c]);
            whr[2*c] = packf(vr.x, vr.y); whr[2*c+1] = packf(vr.z, vr.w);
            whz[2*c] = packf(vz.x, vz.y); whz[2*c+1] = packf(vz.z, vz.w);
            whn[2*c] = packf(vn.x, vn.y); whn[2*c+1] = packf(vn.z, vn.w);
        }
        const float4* X4 = (const float4*)W_ih;   // row stride 16 float4
        #pragma unroll
        for (int c = 0; c < 2; c++) {
            float4 vr = __ldg(&X4[((size_t)(0 * HID + jg)) * 16 + kslice * 2 + c]);
            float4 vz = __ldg(&X4[((size_t)(1 * HID + jg)) * 16 + kslice * 2 + c]);
            float4 vn = __ldg(&X4[((size_t)(2 * HID + jg)) * 16 + kslice * 2 + c]);
            wxr[2*c] = packf(vr.x, vr.y); wxr[2*c+1] = packf(vr.z, vr.w);
            wxz[2*c] = packf(vz.x, vz.y); wxz[2*c+1] = packf(vz.z, vz.w);
            wxn[2*c] = packf(vn.x, vn.y); wxn[2*c+1] = packf(vn.z, vn.w);
        }
    }

    const float bsum_r = b_ih[jg]           + b_hh[jg];
    const float bsum_z = b_ih[HID + jg]     + b_hh[HID + jg];
    const float bx_n   = b_ih[2 * HID + jg];
    const float bh_n   = b_hh[2 * HID + jg];

    // --- h0: each CTA computes the FULL 16x256 group tile locally into h_s (swizzled) ---
    for (int u = tid; u < ROWS * HID; u += 256) {
        int row = u >> 8;
        int col = u & 255;
        int b = rbase + row;
        float v = b_dec[col]
                + hidden[b * 3 + 0] * W_dec[col * 3 + 0]
                + hidden[b * 3 + 1] * W_dec[col * 3 + 1]
                + hidden[b * 3 + 2] * W_dec[col * 3 + 2];
        int csw = (((col >> 2) ^ ((col >> 5) & 7)) << 2) + (col & 3);
        h_s[row * HID + csw] = v;
    }
    // x tile for s=0 is zeros
    *(float4*)(x_s + tid * 4) = make_float4(0.f, 0.f, 0.f, 0.f);
    __syncthreads();

    const int r0 = kslice, r1 = kslice + 8;   // rows this thread owns for gate math

    // x prefetch register: thread owns one float4 of the 16x64 tile
    const int xrow = tid >> 4, xchunk = tid & 15;
    const float4* xp = (const float4*)(input + ((size_t)(rbase + xrow)) * IN_DIM) + xchunk;
    float4 xr4 = __ldg(xp);                       // input[0] -> used at s=1
    const size_t xstride4 = (size_t)BATCH * IN_DIM / 4;

    // ---------------- time-step loop ----------------
    for (int s = 0; s < T_STEPS; s++) {
        if (s > 0) {
            // incremental staging: fetch each producer's 32-col slice as it arrives
            const float4* hsrc = (const float4*)(g_hs + ((size_t)(s - 1) * BATCH + rbase) * HID);
            const unsigned int tgt = 8u * (unsigned int)s;
            unsigned int ready = 0u;
            while (ready != 0xffu) {
                bool ok = (lane < 8) && !((ready >> lane) & 1u)
                          && (ld_acq(grp_cnt + lane * 8) >= tgt);
                unsigned int nb = __ballot_sync(0xffffffffu, ok);
                unsigned int m = nb;
                while (m) {
                    int j = __ffs(m) - 1; m &= m - 1;
                    if (lane < 16) {
                        int c4 = j * 8 + scol;
                        int phys = c4 ^ ((c4 >> 3) & 7);
                        cp_async16(hs_base + (uint32_t)((srow * HID + phys * 4) * 4),
                                   hsrc + srow * 64 + c4);
                    }
                }
                ready |= nb;
            }
            // x tile for this step (xs[s] = input[s-1])
            *(float4*)(x_s + tid * 4) = xr4;
            cp_async_commit_wait();
        }
        if (s <= T_STEPS - 2)
            xr4 = __ldg(xp + (size_t)s * xstride4);

        __syncthreads();

        #pragma unroll 1
        for (int rp = 0; rp < 8; rp++) {
            const float* hra = h_s + (2 * rp)     * HID;
            const float* hrb = h_s + (2 * rp + 1) * HID;
            const float* xra = x_s + (2 * rp)     * IN_DIM;
            const float* xrb = x_s + (2 * rp + 1) * IN_DIM;
            // value order: v0..3 = rowA (r, z, nh, nx), v4..7 = rowB
            ull acc0 = 0, acc1 = 0, acc2 = 0, acc3 = 0;
            ull acc4 = 0, acc5 = 0, acc6 = 0, acc7 = 0;
            #pragma unroll
            for (int c = 0; c < 8; c++) {
                int p = (kslice << 3) + (c ^ kslice);
                ulonglong2 ha = *(const ulonglong2*)(hra + p * 4);
                ulonglong2 hb = *(const ulonglong2*)(hrb + p * 4);
                fma2(acc0, ha.x, whr[2*c]); fma2(acc0, ha.y, whr[2*c+1]);
                fma2(acc1, ha.x, whz[2*c]); fma2(acc1, ha.y, whz[2*c+1]);
                fma2(acc2, ha.x, whn[2*c]); fma2(acc2, ha.y, whn[2*c+1]);
                fma2(acc4, hb.x, whr[2*c]); fma2(acc4, hb.y, whr[2*c+1]);
                fma2(acc5, hb.x, whz[2*c]); fma2(acc5, hb.y, whz[2*c+1]);
                fma2(acc6, hb.x, whn[2*c]); fma2(acc6, hb.y, whn[2*c+1]);
            }
            #pragma unroll
            for (int c = 0; c < 2; c++) {
                ulonglong2 xa = *(const ulonglong2*)(xra + (kslice * 2 + c) * 4);
                ulonglong2 xb = *(const ulonglong2*)(xrb + (kslice * 2 + c) * 4);
                fma2(acc0, xa.x, wxr[2*c]); fma2(acc0, xa.y, wxr[2*c+1]);
                fma2(acc1, xa.x, wxz[2*c]); fma2(acc1, xa.y, wxz[2*c+1]);
                fma2(acc3, xa.x, wxn[2*c]); fma2(acc3, xa.y, wxn[2*c+1]);
                fma2(acc4, xb.x, wxr[2*c]); fma2(acc4, xb.y, wxr[2*c+1]);
                fma2(acc5, xb.x, wxz[2*c]); fma2(acc5, xb.y, wxz[2*c+1]);
                fma2(acc7, xb.x, wxn[2*c]); fma2(acc7, xb.y, wxn[2*c+1]);
            }
            float v0 = redpair(acc0), v1 = redpair(acc1), v2 = redpair(acc2), v3 = redpair(acc3);
            float v4 = redpair(acc4), v5 = redpair(acc5), v6 = redpair(acc6), v7 = redpair(acc7);

            // tournament reduction over 8 k-lanes: 7 shfl, lane k ends with value k
            float w0, w1, w2, w3;
            {
                float t, r;
                t = bit2 ? v0 : v4; r = __shfl_xor_sync(0xffffffffu, t, 4); w0 = (bit2 ? v4 : v0) + r;
                t = bit2 ? v1 : v5; r = __shfl_xor_sync(0xffffffffu, t, 4); w1 = (bit2 ? v5 : v1) + r;
                t = bit2 ? v2 : v6; r = __shfl_xor_sync(0xffffffffu, t, 4); w2 = (bit2 ? v6 : v2) + r;
                t = bit2 ? v3 : v7; r = __shfl_xor_sync(0xffffffffu, t, 4); w3 = (bit2 ? v7 : v3) + r;
            }
            float u0, u1;
            {
                float t, r;
                t = bit1 ? w0 : w2; r = __shfl_xor_sync(0xffffffffu, t, 2); u0 = (bit1 ? w2 : w0) + r;
                t = bit1 ? w1 : w3; r = __shfl_xor_sync(0xffffffffu, t, 2); u1 = (bit1 ? w3 : w1) + r;
            }
            float fin;
            {
                float t = bit0 ? u0 : u1;
                float r = __shfl_xor_sync(0xffffffffu, t, 1);
                fin = (bit0 ? u1 : u0) + r;
            }
            red_w[rp * 8 + red_store_ofs] = fin;
        }
        __syncwarp();

        // --- gate math + state update: this thread owns rows r0, r1 at column jg ---
        float4 ga = *(const float4*)(red_w + r0 * 4);   // r, z, nh, nx for row r0
        float4 gb = *(const float4*)(red_w + r1 * 4);
        float* hdst = g_hs + (size_t)s * BATCH * HID;
        {
            float hold = h_s[r0 * HID + jsw];
            float rg = fast_sig(ga.x + bsum_r);
            float zg = fast_sig(ga.y + bsum_z);
            float ng = fast_tanh(ga.w + bx_n + rg * (ga.z + bh_n));
            hdst[(rbase + r0) * HID + jg] = zg * (hold - ng) + ng;
        }
        {
            float hold = h_s[r1 * HID + jsw];
            float rg = fast_sig(gb.x + bsum_r);
            float zg = fast_sig(gb.y + bsum_z);
            float ng = fast_tanh(gb.w + bx_n + rg * (gb.z + bh_n));
            hdst[(rbase + r1) * HID + jg] = zg * (hold - ng) + ng;
        }

        // per-warp release of OWN producer counter (stores above are ordered before it)
        __syncwarp();
        if (lane == 0) red_release(my_cnt);
    }

    // completion + counter reset for next graph replay
    __syncthreads();
    if (tid == 0) red_release(&g_done[grp * 32]);
    if (jc == 0 && tid == 0) {
        while (ld_acq(&g_done[grp * 32]) < (unsigned int)JCTAS) { }
        #pragma unroll
        for (int j = 0; j < JCTAS; j++) grp_cnt[j * 8] = 0u;
        g_done[grp * 32] = 0u;
        __threadfence();
    }
}

// =====================================================================
// Output GEMM (proven R3 version): 64 rows x 64 o, K=256 in 4 chunks
// =====================================================================
#define XPITCH 68
__global__ void __launch_bounds__(256) k_out(
    const float* __restrict__ W_out,   // [I][H]
    const float* __restrict__ b_out,   // [I]
    float* __restrict__ out)           // [B][T][I]
{
    __shared__ float hs_s[64 * XPITCH];
    __shared__ float ws_s[64 * XPITCH];
    const int tid = threadIdx.x;
    const int tx = tid & 15, ty = tid >> 4;
    const size_t mbase = (size_t)blockIdx.x * 64;

    ull acc[4][4];
    #pragma unroll
    for (int ii = 0; ii < 4; ii++)
        #pragma unroll
        for (int jj = 0; jj < 4; jj++) acc[ii][jj] = 0ULL;

    for (int kc = 0; kc < 4; kc++) {
        const int kofs = kc * 64;
        for (int i = tid; i < 1024; i += 256) {
            int row = i >> 4, c = i & 15;
            float4 v = *(const float4*)(g_hs + (mbase + row) * HID + kofs + c * 4);
            *(float4*)(hs_s + row * XPITCH + c * 4) = v;
        }
        for (int i = tid; i < 1024; i += 256) {
            int row = i >> 4, c = i & 15;
            float4 v = *(const float4*)(W_out + (size_t)row * HID + kofs + c * 4);
            *(float4*)(ws_s + row * XPITCH + c * 4) = v;
        }
        __syncthreads();
        #pragma unroll
        for (int k4 = 0; k4 < 16; k4++) {
            ulonglong2 a[4], w[4];
            #pragma unroll
            for (int ii = 0; ii < 4; ii++)
                a[ii] = *(const ulonglong2*)(hs_s + (ty * 4 + ii) * XPITCH + k4 * 4);
            #pragma unroll
            for (int jj = 0; jj < 4; jj++)
                w[jj] = *(const ulonglong2*)(ws_s + (jj * 16 + tx) * XPITCH + k4 * 4);
            #pragma unroll
            for (int ii = 0; ii < 4; ii++)
                #pragma unroll
                for (int jj = 0; jj < 4; jj++) {
                    fma2(acc[ii][jj], a[ii].x, w[jj].x);
                    fma2(acc[ii][jj], a[ii].y, w[jj].y);
                }
        }
        __syncthreads();
    }

    #pragma unroll
    for (int ii = 0; ii < 4; ii++) {
        size_t m = mbase + ty * 4 + ii;
        size_t t = m >> 8;
        size_t b = m & 255;
        float* op = out + (b * T_STEPS + t) * IN_DIM;
        #pragma unroll
        for (int jj = 0; jj < 4; jj++) {
            int o = jj * 16 + tx;
            op[o] = redpair(acc[ii][jj]) + b_out[o];
        }
    }
}

extern "C" void kernel_launch(void* const* d_in, const int* in_sizes, int n_in,
                              void* d_out, int out_size)
{
    const float* input  = (const float*)d_in[0];
    const float* hidden = (const float*)d_in[1];
    const float* W_dec  = (const float*)d_in[2];
    const float* b_dec  = (const float*)d_in[3];
    const float* W_ih   = (const float*)d_in[4];
    const float* W_hh   = (const float*)d_in[5];
    const float* b_ih   = (const float*)d_in[6];
    const float* b_hh   = (const float*)d_in[7];
    const float* W_out  = (const float*)d_in[8];
    const float* b_out  = (const float*)d_in[9];
    float* out = (float*)d_out;

    k_rec<<<GROUPS * JCTAS, 256>>>(input, hidden, W_dec, b_dec,
                                   W_ih, W_hh, b_ih, b_hh);
    k_out<<<(T_STEPS * BATCH) / 64, 256>>>(W_out, b_out, out);
}

// round 14
// speedup vs baseline: 1.0827x; 1.0827x over previous
#include <cuda_runtime.h>
#include <cstdint>

// Problem constants
#define T_STEPS 2048
#define BATCH   256
#define IN_DIM  64
#define HID     256

// Tiling: 16 row-groups x 8 j-CTAs = 128 CTAs, 256 threads each.
// Thread: ks = lane&15 (16 k-floats), jh = lane>>4, jp = warp*2+jh (2 cols: jp, jp+16).
#define GROUPS   16
#define JCTAS    8
#define ROWS     16
#define JW       32

// Device scratch
__device__ float g_hs[(size_t)T_STEPS * BATCH * HID];   // h trajectory [T][B][H]
__device__ float g_h[2][BATCH * HID];                   // double-buffered state
__device__ unsigned int g_arr[GROUPS * 32];             // per-group monotonic arrival counters

typedef unsigned long long ull;

// ---- packed fp32x2 helpers ----
__device__ __forceinline__ void fma2(ull& acc, ull a, ull b) {
    asm("fma.rn.f32x2 %0, %1, %2, %0;" : "+l"(acc) : "l"(a), "l"(b));
}
__device__ __forceinline__ float redpair(ull v) {
    float lo = __uint_as_float((unsigned int)(v & 0xffffffffULL));
    float hi = __uint_as_float((unsigned int)(v >> 32));
    return lo + hi;
}
__device__ __forceinline__ ull packf(float lo, float hi) {
    return (ull)__float_as_uint(lo) | ((ull)__float_as_uint(hi) << 32);
}
__device__ __forceinline__ float fast_sig(float x) {
    return __fdividef(1.f, 1.f + __expf(-x));
}
__device__ __forceinline__ float fast_tanh(float x) {
    float y;
    asm("tanh.approx.f32 %0, %1;" : "=f"(y) : "f"(x));
    return y;
}
__device__ __forceinline__ unsigned int ld_acq(const unsigned int* p) {
    unsigned int v;
    asm volatile("ld.acquire.gpu.global.u32 %0, [%1];" : "=r"(v) : "l"(p));
    return v;
}
__device__ __forceinline__ void red_release(unsigned int* p) {
    asm volatile("red.release.gpu.global.add.u32 [%0], %1;" :: "l"(p), "r"(1u) : "memory");
}
__device__ __forceinline__ uint32_t smem_u32(const void* p) {
    uint32_t a;
    asm("{ .reg .u64 t; cvta.to.shared.u64 t, %1; cvt.u32.u64 %0, t; }" : "=r"(a) : "l"(p));
    return a;
}
__device__ __forceinline__ void cp_async16(uint32_t saddr, const void* gaddr) {
    asm volatile("cp.async.cg.shared.global [%0], [%1], 16;" :: "r"(saddr), "l"(gaddr) : "memory");
}
__device__ __forceinline__ void cp_async_commit_wait() {
    asm volatile("cp.async.commit_group;" ::: "memory");
    asm volatile("cp.async.wait_group 0;" ::: "memory");
}

// Per-(warp,jh) reduction scratch: 16 rows x 12 floats (8 used, pad 12), JSTRIDE pads
#define RED_JSTRIDE 200    // floats per jh block (16*12=192, +8 pad)
#define RED_WSTRIDE 400    // 2 jh blocks per warp

// =====================================================================
// Persistent recurrent kernel: 2-col/16-k thread layout (halved smem
// traffic), 16-lane tournament reduction, R12 sync scheme.
// =====================================================================
__global__ void __launch_bounds__(256, 1) k_rec(
    const float* __restrict__ input,   // [T][B][I]
    const float* __restrict__ hidden,  // [1][B][3]
    const float* __restrict__ W_dec,   // [H][3]
    const float* __restrict__ b_dec,   // [H]
    const float* __restrict__ W_ih,    // [3H][I]
    const float* __restrict__ W_hh,    // [3H][H]
    const float* __restrict__ b_ih,    // [3H]
    const float* __restrict__ b_hh)    // [3H]
{
    __shared__ float h_s[ROWS * HID];            // 16 KB, XOR-swizzled (16B-chunk)
    __shared__ float x_s[ROWS * IN_DIM];         // 4 KB
    __shared__ float red_s[8 * RED_WSTRIDE];     // 12.5 KB gate scratch

    const int tid = threadIdx.x;
    const int lane = tid & 31;
    const int warp = tid >> 5;
    const int ks = lane & 15;             // k in [ks*16, ks*16+16)
    const int jh = lane >> 4;             // 0..1
    const int jp = warp * 2 + jh;         // 0..15
    const int grp = blockIdx.x >> 3;      // row group
    const int jc = blockIdx.x & 7;
    const int rbase = grp * ROWS;
    const int jgA = jc * JW + jp;         // global hidden columns owned
    const int jgB = jgA + 16;

    unsigned int* my_arr = &g_arr[grp * 32];
    const uint32_t hs_base = smem_u32(h_s);

    // swizzled float offsets of owned columns within an h_s row
    const int jswA = (((jgA >> 2) ^ ((jgA >> 5) & 7)) << 2) + (jgA & 3);
    const int jswB = (((jgB >> 2) ^ ((jgB >> 5) & 7)) << 2) + (jgB & 3);

    const bool b3 = (ks & 8) != 0;
    const bool b2 = (ks & 4) != 0;
    const bool b1 = (ks & 2) != 0;
    const bool b0 = (ks & 1) != 0;
    float* red_w = red_s + warp * RED_WSTRIDE + jh * RED_JSTRIDE;
    // store offset: row = 2rp + b3 (stride 12), col-half b2 (stride 4), gate = ks&3
    const int red_store_base = (b3 ? 12 : 0) + (b2 ? 4 : 0) + (ks & 3);

    // --- load weights into registers (packed f32x2): 2 cols x 3 gates x 16 k ---
    ull whAr[8], whAz[8], whAn[8], whBr[8], whBz[8], whBn[8];
    ull wxAr[2], wxAz[2], wxAn[2], wxBr[2], wxBz[2], wxBn[2];
    {
        const float4* W4 = (const float4*)W_hh;   // row stride 64 float4
        #pragma unroll
        for (int c = 0; c < 4; c++) {
            float4 a_r = __ldg(&W4[((size_t)(0 * HID + jgA)) * 64 + ks * 4 + c]);
            float4 a_z = __ldg(&W4[((size_t)(1 * HID + jgA)) * 64 + ks * 4 + c]);
            float4 a_n = __ldg(&W4[((size_t)(2 * HID + jgA)) * 64 + ks * 4 + c]);
            float4 b_r = __ldg(&W4[((size_t)(0 * HID + jgB)) * 64 + ks * 4 + c]);
            float4 b_z = __ldg(&W4[((size_t)(1 * HID + jgB)) * 64 + ks * 4 + c]);
            float4 b_n = __ldg(&W4[((size_t)(2 * HID + jgB)) * 64 + ks * 4 + c]);
            whAr[2*c] = packf(a_r.x, a_r.y); whAr[2*c+1] = packf(a_r.z, a_r.w);
            whAz[2*c] = packf(a_z.x, a_z.y); whAz[2*c+1] = packf(a_z.z, a_z.w);
            whAn[2*c] = packf(a_n.x, a_n.y); whAn[2*c+1] = packf(a_n.z, a_n.w);
            whBr[2*c] = packf(b_r.x, b_r.y); whBr[2*c+1] = packf(b_r.z, b_r.w);
            whBz[2*c] = packf(b_z.x, b_z.y); whBz[2*c+1] = packf(b_z.z, b_z.w);
            whBn[2*c] = packf(b_n.x, b_n.y); whBn[2*c+1] = packf(b_n.z, b_n.w);
        }
        const float4* X4 = (const float4*)W_ih;   // row stride 16 float4
        {
            float4 a_r = __ldg(&X4[((size_t)(0 * HID + jgA)) * 16 + ks]);
            float4 a_z = __ldg(&X4[((size_t)(1 * HID + jgA)) * 16 + ks]);
            float4 a_n = __ldg(&X4[((size_t)(2 * HID + jgA)) * 16 + ks]);
            float4 b_r = __ldg(&X4[((size_t)(0 * HID + jgB)) * 16 + ks]);
            float4 b_z = __ldg(&X4[((size_t)(1 * HID + jgB)) * 16 + ks]);
            float4 b_n = __ldg(&X4[((size_t)(2 * HID + jgB)) * 16 + ks]);
            wxAr[0] = packf(a_r.x, a_r.y); wxAr[1] = packf(a_r.z, a_r.w);
            wxAz[0] = packf(a_z.x, a_z.y); wxAz[1] = packf(a_z.z, a_z.w);
            wxAn[0] = packf(a_n.x, a_n.y); wxAn[1] = packf(a_n.z, a_n.w);
            wxBr[0] = packf(b_r.x, b_r.y); wxBr[1] = packf(b_r.z, b_r.w);
            wxBz[0] = packf(b_z.x, b_z.y); wxBz[1] = packf(b_z.z, b_z.w);
            wxBn[0] = packf(b_n.x, b_n.y); wxBn[1] = packf(b_n.z, b_n.w);
        }
    }

    const float bsAr = b_ih[jgA]           + b_hh[jgA];
    const float bsAz = b_ih[HID + jgA]     + b_hh[HID + jgA];
    const float bxAn = b_ih[2 * HID + jgA];
    const float bhAn = b_hh[2 * HID + jgA];
    const float bsBr = b_ih[jgB]           + b_hh[jgB];
    const float bsBz = b_ih[HID + jgB]     + b_hh[HID + jgB];
    const float bxBn = b_ih[2 * HID + jgB];
    const float bhBn = b_hh[2 * HID + jgB];

    // --- h0: each CTA writes a 512-elem chunk (rows 2*blockIdx..+2 of g_h[0]) ---
    {
        int base = blockIdx.x * 512;
        for (int u = tid; u < 512; u += 256) {
            int idx = base + u;
            int b = idx >> 8;
            int j = idx & 255;
            g_h[0][idx] = b_dec[j]
                        + hidden[b * 3 + 0] * W_dec[j * 3 + 0]
                        + hidden[b * 3 + 1] * W_dec[j * 3 + 1]
                        + hidden[b * 3 + 2] * W_dec[j * 3 + 2];
        }
    }
    __syncthreads();
    if (lane == 0) red_release(my_arr);   // 8 arrivals per CTA, 64 per group

    // x prefetch register: thread owns one float4 of the 16x64 tile
    const int xrow = tid >> 4, xchunk = tid & 15;
    const float4* xp = (const float4*)(input + ((size_t)(rbase + xrow)) * IN_DIM) + xchunk;
    float4 xr4 = __ldg(xp);                       // input[0] -> used at s=1
    const size_t xstride4 = (size_t)BATCH * IN_DIM / 4;

    // ---------------- time-step loop ----------------
    for (int s = 0; s < T_STEPS; s++) {
        // per-warp wait: h(s) ready when counter >= 64*(s+1)
        if (lane == 0) {
            unsigned int target = 64u * (unsigned int)(s + 1);
            while (ld_acq(my_arr) < target) { }
        }
        __syncwarp();

        // stage h tile [16][256] from g_h[s&1] via cp.async (swizzled)
        {
            const float4* hsrc = (const float4*)(g_h[s & 1] + (size_t)rbase * HID);
            #pragma unroll
            for (int it = 0; it < 4; it++) {
                int idx = tid + it * 256;            // 0..1023
                int row = idx >> 6, c4 = idx & 63;
                int phys = c4 ^ ((c4 >> 3) & 7);
                cp_async16(hs_base + (uint32_t)((row * HID + phys * 4) * 4), hsrc + idx);
            }
        }
        // stage x tile [16][64] (xs[0]=0, xs[s]=input[s-1])
        if (s == 0) {
            *(float4*)(x_s + tid * 4) = make_float4(0.f, 0.f, 0.f, 0.f);
        } else {
            *(float4*)(x_s + tid * 4) = xr4;
        }
        if (s <= T_STEPS - 2)
            xr4 = __ldg(xp + (size_t)s * xstride4);

        cp_async_commit_wait();
        __syncthreads();

        #pragma unroll 1
        for (int rp = 0; rp < 8; rp++) {
            const float* hra = h_s + (2 * rp)     * HID;
            const float* hrb = h_s + (2 * rp + 1) * HID;
            const float* xra = x_s + (2 * rp)     * IN_DIM;
            const float* xrb = x_s + (2 * rp + 1) * IN_DIM;
            // 16 accumulators: rows a/b x cols A/B x (r, z, nh, nx)
            ull aA_r = 0, aA_z = 0, aA_n = 0, aA_x = 0;
            ull aB_r = 0, aB_z = 0, aB_n = 0, aB_x = 0;
            ull bA_r = 0, bA_z = 0, bA_n = 0, bA_x = 0;
            ull bB_r = 0, bB_z = 0, bB_n = 0, bB_x = 0;
            #pragma unroll
            for (int c = 0; c < 4; c++) {
                int c4 = ks * 4 + c;
                int p = c4 ^ ((c4 >> 3) & 7);
                ulonglong2 ha = *(const ulonglong2*)(hra + p * 4);
                ulonglong2 hb = *(const ulonglong2*)(hrb + p * 4);
                fma2(aA_r, ha.x, whAr[2*c]); fma2(aA_r, ha.y, whAr[2*c+1]);
                fma2(aA_z, ha.x, whAz[2*c]); fma2(aA_z, ha.y, whAz[2*c+1]);
                fma2(aA_n, ha.x, whAn[2*c]); fma2(aA_n, ha.y, whAn[2*c+1]);
                fma2(aB_r, ha.x, whBr[2*c]); fma2(aB_r, ha.y, whBr[2*c+1]);
                fma2(aB_z, ha.x, whBz[2*c]); fma2(aB_z, ha.y, whBz[2*c+1]);
                fma2(aB_n, ha.x, whBn[2*c]); fma2(aB_n, ha.y, whBn[2*c+1]);
                fma2(bA_r, hb.x, whAr[2*c]); fma2(bA_r, hb.y, whAr[2*c+1]);
                fma2(bA_z, hb.x, whAz[2*c]); fma2(bA_z, hb.y, whAz[2*c+1]);
                fma2(bA_n, hb.x, whAn[2*c]); fma2(bA_n, hb.y, whAn[2*c+1]);
                fma2(bB_r, hb.x, whBr[2*c]); fma2(bB_r, hb.y, whBr[2*c+1]);
                fma2(bB_z, hb.x, whBz[2*c]); fma2(bB_z, hb.y, whBz[2*c+1]);
                fma2(bB_n, hb.x, whBn[2*c]); fma2(bB_n, hb.y, whBn[2*c+1]);
            }
            {
                ulonglong2 xa = *(const ulonglong2*)(xra + ks * 4);
                ulonglong2 xb = *(const ulonglong2*)(xrb + ks * 4);
                fma2(aA_r, xa.x, wxAr[0]); fma2(aA_r, xa.y, wxAr[1]);
                fma2(aA_z, xa.x, wxAz[0]); fma2(aA_z, xa.y, wxAz[1]);
                fma2(aA_x, xa.x, wxAn[0]); fma2(aA_x, xa.y, wxAn[1]);
                fma2(aB_r, xa.x, wxBr[0]); fma2(aB_r, xa.y, wxBr[1]);
                fma2(aB_z, xa.x, wxBz[0]); fma2(aB_z, xa.y, wxBz[1]);
                fma2(aB_x, xa.x, wxBn[0]); fma2(aB_x, xa.y, wxBn[1]);
                fma2(bA_r, xb.x, wxAr[0]); fma2(bA_r, xb.y, wxAr[1]);
                fma2(bA_z, xb.x, wxAz[0]); fma2(bA_z, xb.y, wxAz[1]);
                fma2(bA_x, xb.x, wxAn[0]); fma2(bA_x, xb.y, wxAn[1]);
                fma2(bB_r, xb.x, wxBr[0]); fma2(bB_r, xb.y, wxBr[1]);
                fma2(bB_z, xb.x, wxBz[0]); fma2(bB_z, xb.y, wxBz[1]);
                fma2(bB_x, xb.x, wxBn[0]); fma2(bB_x, xb.y, wxBn[1]);
            }
            // value index v = rowbit*8 + colbit*4 + gate (r,z,nh,nx)
            float v[16];
            v[0]  = redpair(aA_r); v[1]  = redpair(aA_z); v[2]  = redpair(aA_n); v[3]  = redpair(aA_x);
            v[4]  = redpair(aB_r); v[5]  = redpair(aB_z); v[6]  = redpair(aB_n); v[7]  = redpair(aB_x);
            v[8]  = redpair(bA_r); v[9]  = redpair(bA_z); v[10] = redpair(bA_n); v[11] = redpair(bA_x);
            v[12] = redpair(bB_r); v[13] = redpair(bB_z); v[14] = redpair(bB_n); v[15] = redpair(bB_x);

            // 16-lane tournament: 15 shfl, lane ks ends with value index ks
            float w8[8];
            #pragma unroll
            for (int i = 0; i < 8; i++) {
                float t = b3 ? v[i] : v[i + 8];
                float r = __shfl_xor_sync(0xffffffffu, t, 8);
                w8[i] = (b3 ? v[i + 8] : v[i]) + r;
            }
            float w4[4];
            #pragma unroll
            for (int i = 0; i < 4; i++) {
                float t = b2 ? w8[i] : w8[i + 4];
                float r = __shfl_xor_sync(0xffffffffu, t, 4);
                w4[i] = (b2 ? w8[i + 4] : w8[i]) + r;
            }
            float w2[2];
            #pragma unroll
            for (int i = 0; i < 2; i++) {
                float t = b1 ? w4[i] : w4[i + 2];
                float r = __shfl_xor_sync(0xffffffffu, t, 2);
                w2[i] = (b1 ? w4[i + 2] : w4[i]) + r;
            }
            float fin;
            {
                float t = b0 ? w2[0] : w2[1];
                float r = __shfl_xor_sync(0xffffffffu, t, 1);
                fin = (b0 ? w2[1] : w2[0]) + r;
            }
            red_w[rp * 24 + red_store_base] = fin;   // row stride 12, 2 rows per rp
        }
        __syncwarp();

        // --- gate math: thread owns row ks, cols jgA and jgB ---
        float4 ga = *(const float4*)(red_w + ks * 12);       // colA: r, z, nh, nx
        float4 gb = *(const float4*)(red_w + ks * 12 + 4);   // colB
        float* hnxt = g_h[(s & 1) ^ 1];
        float hnA, hnB;
        {
            float hold = h_s[ks * HID + jswA];
            float rg = fast_sig(ga.x + bsAr);
            float zg = fast_sig(ga.y + bsAz);
            float ng = fast_tanh(ga.w + bxAn + rg * (ga.z + bhAn));
            hnA = zg * (hold - ng) + ng;
            hnxt[(rbase + ks) * HID + jgA] = hnA;
        }
        {
            float hold = h_s[ks * HID + jswB];
            float rg = fast_sig(gb.x + bsBr);
            float zg = fast_sig(gb.y + bsBz);
            float ng = fast_tanh(gb.w + bxBn + rg * (gb.z + bhBn));
            hnB = zg * (hold - ng) + ng;
            hnxt[(rbase + ks) * HID + jgB] = hnB;
        }

        // release FIRST (critical path), then trajectory stores (off-path)
        __syncwarp();
        if (lane == 0) red_release(my_arr);
        g_hs[((size_t)s * BATCH + rbase + ks) * HID + jgA] = hnA;
        g_hs[((size_t)s * BATCH + rbase + ks) * HID + jgB] = hnB;
    }

    // reset counter for next graph replay (one CTA per group)
    if (jc == 0 && tid == 0) {
        unsigned int fin = 64u * (unsigned int)(T_STEPS + 1);
        while (ld_acq(my_arr) < fin) { }
        *my_arr = 0u;
        __threadfence();
    }
}

// =====================================================================
// Output GEMM (proven R3 version): 64 rows x 64 o, K=256 in 4 chunks
// =====================================================================
#define XPITCH 68
__global__ void __launch_bounds__(256) k_out(
    const float* __restrict__ W_out,   // [I][H]
    const float* __restrict__ b_out,   // [I]
    float* __restrict__ out)           // [B][T][I]
{
    __shared__ float hs_s[64 * XPITCH];
    __shared__ float ws_s[64 * XPITCH];
    const int tid = threadIdx.x;
    const int tx = tid & 15, ty = tid >> 4;
    const size_t mbase = (size_t)blockIdx.x * 64;

    ull acc[4][4];
    #pragma unroll
    for (int ii = 0; ii < 4; ii++)
        #pragma unroll
        for (int jj = 0; jj < 4; jj++) acc[ii][jj] = 0ULL;

    for (int kc = 0; kc < 4; kc++) {
        const int kofs = kc * 64;
        for (int i = tid; i < 1024; i += 256) {
            int row = i >> 4, c = i & 15;
            float4 v = *(const float4*)(g_hs + (mbase + row) * HID + kofs + c * 4);
            *(float4*)(hs_s + row * XPITCH + c * 4) = v;
        }
        for (int i = tid; i < 1024; i += 256) {
            int row = i >> 4, c = i & 15;
            float4 v = *(const float4*)(W_out + (size_t)row * HID + kofs + c * 4);
            *(float4*)(ws_s + row * XPITCH + c * 4) = v;
        }
        __syncthreads();
        #pragma unroll
        for (int k4 = 0; k4 < 16; k4++) {
            ulonglong2 a[4], w[4];
            #pragma unroll
            for (int ii = 0; ii < 4; ii++)
                a[ii] = *(const ulonglong2*)(hs_s + (ty * 4 + ii) * XPITCH + k4 * 4);
            #pragma unroll
            for (int jj = 0; jj < 4; jj++)
                w[jj] = *(const ulonglong2*)(ws_s + (jj * 16 + tx) * XPITCH + k4 * 4);
            #pragma unroll
            for (int ii = 0; ii < 4; ii++)
                #pragma unroll
                for (int jj = 0; jj < 4; jj++) {
                    fma2(acc[ii][jj], a[ii].x, w[jj].x);
                    fma2(acc[ii][jj], a[ii].y, w[jj].y);
                }
        }
        __syncthreads();
    }

    #pragma unroll
    for (int ii = 0; ii < 4; ii++) {
        size_t m = mbase + ty * 4 + ii;
        size_t t = m >> 8;
        size_t b = m & 255;
        float* op = out + (b * T_STEPS + t) * IN_DIM;
        #pragma unroll
        for (int jj = 0; jj < 4; jj++) {
            int o = jj * 16 + tx;
            op[o] = redpair(acc[ii][jj]) + b_out[o];
        }
    }
}

extern "C" void kernel_launch(void* const* d_in, const int* in_sizes, int n_in,
                              void* d_out, int out_size)
{
    const float* input  = (const float*)d_in[0];
    const float* hidden = (const float*)d_in[1];
    const float* W_dec  = (const float*)d_in[2];
    const float* b_dec  = (const float*)d_in[3];
    const float* W_ih   = (const float*)d_in[4];
    const float* W_hh   = (const float*)d_in[5];
    const float* b_ih   = (const float*)d_in[6];
    const float* b_hh   = (const float*)d_in[7];
    const float* W_out  = (const float*)d_in[8];
    const float* b_out  = (const float*)d_in[9];
    float* out = (float*)d_out;

    k_rec<<<GROUPS * JCTAS, 256>>>(input, hidden, W_dec, b_dec,
                                   W_ih, W_hh, b_ih, b_hh);
    k_out<<<(T_STEPS * BATCH) / 64, 256>>>(W_out, b_out, out);
}

// round 15
// speedup vs baseline: 1.2818x; 1.1839x over previous
#include <cuda_runtime.h>
#include <cstdint>

// Problem constants
#define T_STEPS 2048
#define BATCH   256
#define IN_DIM  64
#define HID     256
#define GROUPS  16
#define JCTAS   8
#define ROWS    16

// smem layout (4-byte units)
#define OFF_HHI  0          // h tile hi, frag layout: 32 chunks x 32 lanes x 4 = 4096
#define OFF_HLO  4096
#define OFF_XHI  8192       // x tile hi: 8 chunks x 32 x 4 = 1024
#define OFF_XLO  9216
#define OFF_BLOH 10240      // W_hh lo frags: 8 warps x 3 gates x 16 chunks x 64 = 24576
#define OFF_BLOX 34816      // W_ih lo frags: 8 x 3 x 4 x 64 = 6144
#define OFF_PART 40960      // cross-warp partials: 128 x 20 = 2560
#define SMEM_UNITS 43520
#define SMEM_BYTES (SMEM_UNITS*4)

// Device scratch
__device__ float g_hs[(size_t)T_STEPS * BATCH * HID];          // trajectory [T][B][H]
__device__ unsigned int g_hfrag_hi[2][GROUPS * 4096];          // h state, tf32 frag layout
__device__ unsigned int g_hfrag_lo[2][GROUPS * 4096];
__device__ unsigned int g_xfrag_hi[(size_t)T_STEPS * GROUPS * 1024];
__device__ unsigned int g_xfrag_lo[(size_t)T_STEPS * GROUPS * 1024];
__device__ unsigned int g_arr[GROUPS * 32];                    // per-group arrival counters

typedef unsigned long long ull;

// ---- helpers ----
__device__ __forceinline__ uint32_t f2tf32(float f) {
    uint32_t u; asm("cvt.rna.tf32.f32 %0, %1;" : "=r"(u) : "f"(f)); return u;
}
__device__ __forceinline__ float fast_sig(float x) {
    return __fdividef(1.f, 1.f + __expf(-x));
}
__device__ __forceinline__ float fast_tanh(float x) {
    float y; asm("tanh.approx.f32 %0, %1;" : "=f"(y) : "f"(x)); return y;
}
__device__ __forceinline__ unsigned int ld_acq(const unsigned int* p) {
    unsigned int v;
    asm volatile("ld.acquire.gpu.global.u32 %0, [%1];" : "=r"(v) : "l"(p));
    return v;
}
__device__ __forceinline__ void red_release(unsigned int* p) {
    asm volatile("red.release.gpu.global.add.u32 [%0], %1;" :: "l"(p), "r"(1u) : "memory");
}
__device__ __forceinline__ uint32_t smem_u32(const void* p) {
    uint32_t a;
    asm("{ .reg .u64 t; cvta.to.shared.u64 t, %1; cvt.u32.u64 %0, t; }" : "=r"(a) : "l"(p));
    return a;
}
__device__ __forceinline__ void cp_async16(uint32_t saddr, const void* gaddr) {
    asm volatile("cp.async.cg.shared.global [%0], [%1], 16;" :: "r"(saddr), "l"(gaddr) : "memory");
}
__device__ __forceinline__ void cp_async_commit_wait() {
    asm volatile("cp.async.commit_group;" ::: "memory");
    asm volatile("cp.async.wait_group 0;" ::: "memory");
}
// packed fp32x2 FMA (k_out)
__device__ __forceinline__ void fma2(ull& acc, ull a, ull b) {
    asm("fma.rn.f32x2 %0, %1, %2, %0;" : "+l"(acc) : "l"(a), "l"(b));
}
__device__ __forceinline__ float redpair(ull v) {
    float lo = __uint_as_float((unsigned int)(v & 0xffffffffULL));
    float hi = __uint_as_float((unsigned int)(v >> 32));
    return lo + hi;
}

// m16n8k8 TF32 mma, D += A*B
#define MMA4(D, A, B0, B1) \
    asm volatile("mma.sync.aligned.m16n8k8.row.col.f32.tf32.tf32.f32 " \
                 "{%0,%1,%2,%3},{%4,%5,%6,%7},{%8,%9},{%0,%1,%2,%3};" \
                 : "+f"(D[0]), "+f"(D[1]), "+f"(D[2]), "+f"(D[3]) \
                 : "r"((A).x), "r"((A).y), "r"((A).z), "r"((A).w), "r"(B0), "r"(B1))

// =====================================================================
// Pre-kernel: convert xs[t] = (t==0 ? 0 : input[t-1]) into tf32 hi/lo
// fragment-layout arrays. One thread per (t, b, i4).
// =====================================================================
__global__ void __launch_bounds__(256) k_xprep(const float* __restrict__ input)
{
    size_t gid = (size_t)blockIdx.x * 256 + threadIdx.x;   // T*B*16 total
    int i4 = (int)(gid & 15);
    size_t tb = gid >> 4;
    int b = (int)(tb & 255);
    int t = (int)(tb >> 8);
    if (t >= T_STEPS) return;

    float vals[4];
    if (t == 0) {
        vals[0] = vals[1] = vals[2] = vals[3] = 0.f;
    } else {
        float4 v = *(const float4*)(input + (((size_t)(t - 1) * BATCH + b) * IN_DIM) + i4 * 4);
        vals[0] = v.x; vals[1] = v.y; vals[2] = v.z; vals[3] = v.w;
    }
    int grp = b >> 4, row = b & 15;
    int rowhalf = row >> 3;
    size_t base = ((size_t)t * GROUPS + grp) * 1024;
    #pragma unroll
    for (int j = 0; j < 4; j++) {
        int i = i4 * 4 + j;
        int xc = i >> 3, half = (i >> 2) & 1, tig = i & 3;
        int e = half * 2 + rowhalf;
        int l = (row & 7) * 4 + tig;
        float f = vals[j];
        uint32_t hi = f2tf32(f);
        uint32_t lo = f2tf32(f - __uint_as_float(hi));
        g_xfrag_hi[base + (size_t)(xc * 32 + l) * 4 + e] = hi;
        g_xfrag_lo[base + (size_t)(xc * 32 + l) * 4 + e] = lo;
    }
}

// =====================================================================
// Persistent recurrent kernel: TF32 mma (3-product split), fragment-
// layout h exchange, R14 counter sync.
// Warp w: col-tile t = w&3 (8 cols), K-half kh = w>>2.
// =====================================================================
__global__ void __launch_bounds__(256, 1) k_rec(
    const float* __restrict__ input,
    const float* __restrict__ hidden,  // [1][B][3]
    const float* __restrict__ W_dec,   // [H][3]
    const float* __restrict__ b_dec,   // [H]
    const float* __restrict__ W_ih,    // [3H][I]
    const float* __restrict__ W_hh,    // [3H][H]
    const float* __restrict__ b_ih,    // [3H]
    const float* __restrict__ b_hh)    // [3H]
{
    extern __shared__ unsigned int smu[];
    float* smf = (float*)smu;
    const uint32_t sbase = smem_u32(smu);

    const int tid = threadIdx.x;
    const int lane = tid & 31;
    const int warp = tid >> 5;
    const int t = warp & 3;           // col tile (8 cols)
    const int kh = warp >> 2;         // K half
    const int grp = blockIdx.x >> 3;
    const int jc = blockIdx.x & 7;
    const int rbase = grp * ROWS;

    unsigned int* my_arr = &g_arr[grp * 32];

    // --- B fragments: hi in registers, lo in smem ---
    uint32_t bh_h[3][16][2];
    uint32_t bh_x[3][4][2];
    {
        const int ncol = jc * 32 + t * 8 + (lane >> 2);
        const int klo = lane & 3;
        #pragma unroll
        for (int g = 0; g < 3; g++) {
            #pragma unroll
            for (int cc = 0; cc < 16; cc++) {
                size_t wrow = (size_t)(g * HID + ncol) * HID;
                int k0 = kh * 128 + cc * 8 + klo;
                float w0 = W_hh[wrow + k0];
                float w1 = W_hh[wrow + k0 + 4];
                uint32_t h0 = f2tf32(w0), h1 = f2tf32(w1);
                bh_h[g][cc][0] = h0; bh_h[g][cc][1] = h1;
                int bi = OFF_BLOH + (((warp * 3 + g) * 16 + cc) * 64 + lane * 2);
                smu[bi]     = f2tf32(w0 - __uint_as_float(h0));
                smu[bi + 1] = f2tf32(w1 - __uint_as_float(h1));
            }
            #pragma unroll
            for (int cc = 0; cc < 4; cc++) {
                size_t wrow = (size_t)(g * HID + ncol) * IN_DIM;
                int k0 = kh * 32 + cc * 8 + klo;
                float w0 = W_ih[wrow + k0];
                float w1 = W_ih[wrow + k0 + 4];
                uint32_t h0 = f2tf32(w0), h1 = f2tf32(w1);
                bh_x[g][cc][0] = h0; bh_x[g][cc][1] = h1;
                int bi = OFF_BLOX + (((warp * 3 + g) * 4 + cc) * 64 + lane * 2);
                smu[bi]     = f2tf32(w0 - __uint_as_float(h0));
                smu[bi + 1] = f2tf32(w1 - __uint_as_float(h1));
            }
        }
    }

    // gate-phase constants (meaningful for warps 0-3; computed by all)
    const int grow = lane >> 2;                 // local row 0..7 (and +8)
    const int q = lane & 3;
    const int colg = jc * 32 + t * 8 + 2 * q;   // global col of D c0/c2
    const float bs_r0 = b_ih[colg]             + b_hh[colg];
    const float bs_r1 = b_ih[colg + 1]         + b_hh[colg + 1];
    const float bs_z0 = b_ih[HID + colg]       + b_hh[HID + colg];
    const float bs_z1 = b_ih[HID + colg + 1]   + b_hh[HID + colg + 1];
    const float bxn0  = b_ih[2 * HID + colg];
    const float bxn1  = b_ih[2 * HID + colg + 1];
    const float bhn0  = b_hh[2 * HID + colg];
    const float bhn1  = b_hh[2 * HID + colg + 1];
    // frag coords of the 4 owned positions
    const int gch = colg >> 3;
    const int ghalf = (colg >> 2) & 1;
    const int gl0 = grow * 4 + (colg & 3);
    const int gbidx = (gch * 32 + gl0) * 4 + 2 * ghalf;   // (row,col0)/(row+8,col0) pair

    // --- h0 -> g_hfrag[0] (each CTA: its 16 rows x 32 cols) ---
    {
        for (int u = tid; u < 512; u += 256) {
            int row = u >> 5;
            int cl = u & 31;
            int cg = jc * 32 + cl;
            int b = rbase + row;
            float v = b_dec[cg]
                    + hidden[b * 3 + 0] * W_dec[cg * 3 + 0]
                    + hidden[b * 3 + 1] * W_dec[cg * 3 + 1]
                    + hidden[b * 3 + 2] * W_dec[cg * 3 + 2];
            uint32_t hi = f2tf32(v);
            uint32_t lo = f2tf32(v - __uint_as_float(hi));
            int ch = cg >> 3, half = (cg >> 2) & 1, tig = cg & 3;
            int e = half * 2 + (row >> 3);
            int l = (row & 7) * 4 + tig;
            int idx = grp * 4096 + (ch * 32 + l) * 4 + e;
            g_hfrag_hi[0][idx] = hi;
            g_hfrag_lo[0][idx] = lo;
        }
    }
    __syncthreads();
    if (warp < 4 && lane == 0) red_release(my_arr);   // 4/CTA -> 32/group

    // ---------------- time-step loop ----------------
    for (int s = 0; s < T_STEPS; s++) {
        const int buf = s & 1;
        // wait h(s)
        if (lane == 0) {
            unsigned int tgt = 32u * (unsigned int)(s + 1);
            while (ld_acq(my_arr) < tgt) { }
        }
        __syncwarp();

        // stage h (hi+lo, 32KB) + x (hi+lo, 8KB) tiles, frag layout verbatim
        {
            const uint4* shi = (const uint4*)(g_hfrag_hi[buf] + grp * 4096);
            const uint4* slo = (const uint4*)(g_hfrag_lo[buf] + grp * 4096);
            #pragma unroll
            for (int it = 0; it < 4; it++) {
                int ci = tid + it * 256;
                cp_async16(sbase + (OFF_HHI + ci * 4) * 4, shi + ci);
                cp_async16(sbase + (OFF_HLO + ci * 4) * 4, slo + ci);
            }
            const uint4* xhi = (const uint4*)(g_xfrag_hi + ((size_t)s * GROUPS + grp) * 1024);
            const uint4* xlo = (const uint4*)(g_xfrag_lo + ((size_t)s * GROUPS + grp) * 1024);
            cp_async16(sbase + (OFF_XHI + tid * 4) * 4, xhi + tid);
            cp_async16(sbase + (OFF_XLO + tid * 4) * 4, xlo + tid);
        }
        cp_async_commit_wait();
        __syncthreads();

        // --- mma: 3-product tf32 chains into 4 D fragments ---
        float dr[4] = {0.f, 0.f, 0.f, 0.f};
        float dz[4] = {0.f, 0.f, 0.f, 0.f};
        float dnh[4] = {0.f, 0.f, 0.f, 0.f};
        float dnx[4] = {0.f, 0.f, 0.f, 0.f};

        const uint4* Ahh = (const uint4*)(smu + OFF_HHI);
        const uint4* Ahl = (const uint4*)(smu + OFF_HLO);
        #pragma unroll
        for (int cc = 0; cc < 16; cc++) {
            int ai = (kh * 16 + cc) * 32 + lane;
            uint4 ah = Ahh[ai];
            uint4 al = Ahl[ai];
            {
                uint2 bl = *(const uint2*)(smu + OFF_BLOH + (((warp * 3 + 0) * 16 + cc) * 64 + lane * 2));
                MMA4(dr, ah, bh_h[0][cc][0], bh_h[0][cc][1]);
                MMA4(dr, al, bh_h[0][cc][0], bh_h[0][cc][1]);
                MMA4(dr, ah, bl.x, bl.y);
            }
            {
                uint2 bl = *(const uint2*)(smu + OFF_BLOH + (((warp * 3 + 1) * 16 + cc) * 64 + lane * 2));
                MMA4(dz, ah, bh_h[1][cc][0], bh_h[1][cc][1]);
                MMA4(dz, al, bh_h[1][cc][0], bh_h[1][cc][1]);
                MMA4(dz, ah, bl.x, bl.y);
            }
            {
                uint2 bl = *(const uint2*)(smu + OFF_BLOH + (((warp * 3 + 2) * 16 + cc) * 64 + lane * 2));
                MMA4(dnh, ah, bh_h[2][cc][0], bh_h[2][cc][1]);
                MMA4(dnh, al, bh_h[2][cc][0], bh_h[2][cc][1]);
                MMA4(dnh, ah, bl.x, bl.y);
            }
        }
        const uint4* Axh = (const uint4*)(smu + OFF_XHI);
        const uint4* Axl = (const uint4*)(smu + OFF_XLO);
        #pragma unroll
        for (int cc = 0; cc < 4; cc++) {
            int ai = (kh * 4 + cc) * 32 + lane;
            uint4 ah = Axh[ai];
            uint4 al = Axl[ai];
            {
                uint2 bl = *(const uint2*)(smu + OFF_BLOX + (((warp * 3 + 0) * 4 + cc) * 64 + lane * 2));
                MMA4(dr, ah, bh_x[0][cc][0], bh_x[0][cc][1]);
                MMA4(dr, al, bh_x[0][cc][0], bh_x[0][cc][1]);
                MMA4(dr, ah, bl.x, bl.y);
            }
            {
                uint2 bl = *(const uint2*)(smu + OFF_BLOX + (((warp * 3 + 1) * 4 + cc) * 64 + lane * 2));
                MMA4(dz, ah, bh_x[1][cc][0], bh_x[1][cc][1]);
                MMA4(dz, al, bh_x[1][cc][0], bh_x[1][cc][1]);
                MMA4(dz, ah, bl.x, bl.y);
            }
            {
                uint2 bl = *(const uint2*)(smu + OFF_BLOX + (((warp * 3 + 2) * 4 + cc) * 64 + lane * 2));
                MMA4(dnx, ah, bh_x[2][cc][0], bh_x[2][cc][1]);
                MMA4(dnx, al, bh_x[2][cc][0], bh_x[2][cc][1]);
                MMA4(dnx, ah, bl.x, bl.y);
            }
        }

        // --- cross-K-half reduction: warps 4-7 export partials ---
        if (warp >= 4) {
            float* pp = smf + OFF_PART + ((warp - 4) * 32 + lane) * 20;
            *(float4*)(pp)      = make_float4(dr[0], dr[1], dr[2], dr[3]);
            *(float4*)(pp + 4)  = make_float4(dz[0], dz[1], dz[2], dz[3]);
            *(float4*)(pp + 8)  = make_float4(dnh[0], dnh[1], dnh[2], dnh[3]);
            *(float4*)(pp + 12) = make_float4(dnx[0], dnx[1], dnx[2], dnx[3]);
        }
        __syncthreads();

        if (warp < 4) {
            const float* pp = smf + OFF_PART + (warp * 32 + lane) * 20;
            float4 pr = *(const float4*)(pp);
            float4 pz = *(const float4*)(pp + 4);
            float4 pn = *(const float4*)(pp + 8);
            float4 px = *(const float4*)(pp + 12);
            dr[0] += pr.x; dr[1] += pr.y; dr[2] += pr.z; dr[3] += pr.w;
            dz[0] += pz.x; dz[1] += pz.y; dz[2] += pz.z; dz[3] += pz.w;
            dnh[0] += pn.x; dnh[1] += pn.y; dnh[2] += pn.z; dnh[3] += pn.w;
            dnx[0] += px.x; dnx[1] += px.y; dnx[2] += px.z; dnx[3] += px.w;

            // h_old (4 positions) from staged frag tiles
            float2 hA = *(const float2*)(smf + OFF_HHI + gbidx);
            float2 lA = *(const float2*)(smf + OFF_HLO + gbidx);
            float2 hB = *(const float2*)(smf + OFF_HHI + gbidx + 4);
            float2 lB = *(const float2*)(smf + OFF_HLO + gbidx + 4);
            float hold00 = hA.x + lA.x;   // (row,   col0)
            float hold10 = hA.y + lA.y;   // (row+8, col0)
            float hold01 = hB.x + lB.x;   // (row,   col1)
            float hold11 = hB.y + lB.y;   // (row+8, col1)

            // gates: D mapping c0=(row,col0), c1=(row,col1), c2=(row+8,col0), c3=(row+8,col1)
            float rg, zg, ng;
            rg = fast_sig(dr[0] + bs_r0); zg = fast_sig(dz[0] + bs_z0);
            ng = fast_tanh(dnx[0] + bxn0 + rg * (dnh[0] + bhn0));
            float hn00 = zg * (hold00 - ng) + ng;
            rg = fast_sig(dr[1] + bs_r1); zg = fast_sig(dz[1] + bs_z1);
            ng = fast_tanh(dnx[1] + bxn1 + rg * (dnh[1] + bhn1));
            float hn01 = zg * (hold01 - ng) + ng;
            rg = fast_sig(dr[2] + bs_r0); zg = fast_sig(dz[2] + bs_z0);
            ng = fast_tanh(dnx[2] + bxn0 + rg * (dnh[2] + bhn0));
            float hn10 = zg * (hold10 - ng) + ng;
            rg = fast_sig(dr[3] + bs_r1); zg = fast_sig(dz[3] + bs_z1);
            ng = fast_tanh(dnx[3] + bxn1 + rg * (dnh[3] + bhn1));
            float hn11 = zg * (hold11 - ng) + ng;

            // h_new -> frag arrays (hi/lo) for next step
            uint32_t u00 = f2tf32(hn00), u01 = f2tf32(hn01);
            uint32_t u10 = f2tf32(hn10), u11 = f2tf32(hn11);
            uint32_t v00 = f2tf32(hn00 - __uint_as_float(u00));
            uint32_t v01 = f2tf32(hn01 - __uint_as_float(u01));
            uint32_t v10 = f2tf32(hn10 - __uint_as_float(u10));
            uint32_t v11 = f2tf32(hn11 - __uint_as_float(u11));
            unsigned int* dhi = g_hfrag_hi[buf ^ 1] + grp * 4096;
            unsigned int* dlo = g_hfrag_lo[buf ^ 1] + grp * 4096;
            *(uint2*)(dhi + gbidx)     = make_uint2(u00, u10);
            *(uint2*)(dhi + gbidx + 4) = make_uint2(u01, u11);
            *(uint2*)(dlo + gbidx)     = make_uint2(v00, v10);
            *(uint2*)(dlo + gbidx + 4) = make_uint2(v01, v11);

            __syncwarp();
            if (lane == 0) red_release(my_arr);

            // trajectory (off critical path)
            float* hd = g_hs + ((size_t)s * BATCH + rbase + grow) * HID + colg;
            *(float2*)hd = make_float2(hn00, hn01);
            *(float2*)(hd + 8 * HID) = make_float2(hn10, hn11);
        }
    }

    // counter reset for next graph replay
    if (jc == 0 && tid == 0) {
        unsigned int fin = 32u * (unsigned int)(T_STEPS + 1);
        while (ld_acq(my_arr) < fin) { }
        *my_arr = 0u;
        __threadfence();
    }
}

// =====================================================================
// Output GEMM (proven R3 version): 64 rows x 64 o, K=256 in 4 chunks
// =====================================================================
#define XPITCH 68
__global__ void __launch_bounds__(256) k_out(
    const float* __restrict__ W_out,   // [I][H]
    const float* __restrict__ b_out,   // [I]
    float* __restrict__ out)           // [B][T][I]
{
    __shared__ float hs_s[64 * XPITCH];
    __shared__ float ws_s[64 * XPITCH];
    const int tid = threadIdx.x;
    const int tx = tid & 15, ty = tid >> 4;
    const size_t mbase = (size_t)blockIdx.x * 64;

    ull acc[4][4];
    #pragma unroll
    for (int ii = 0; ii < 4; ii++)
        #pragma unroll
        for (int jj = 0; jj < 4; jj++) acc[ii][jj] = 0ULL;

    for (int kc = 0; kc < 4; kc++) {
        const int kofs = kc * 64;
        for (int i = tid; i < 1024; i += 256) {
            int row = i >> 4, c = i & 15;
            float4 v = *(const float4*)(g_hs + (mbase + row) * HID + kofs + c * 4);
            *(float4*)(hs_s + row * XPITCH + c * 4) = v;
        }
        for (int i = tid; i < 1024; i += 256) {
            int row = i >> 4, c = i & 15;
            float4 v = *(const float4*)(W_out + (size_t)row * HID + kofs + c * 4);
            *(float4*)(ws_s + row * XPITCH + c * 4) = v;
        }
        __syncthreads();
        #pragma unroll
        for (int k4 = 0; k4 < 16; k4++) {
            ulonglong2 a[4], w[4];
            #pragma unroll
            for (int ii = 0; ii < 4; ii++)
                a[ii] = *(const ulonglong2*)(hs_s + (ty * 4 + ii) * XPITCH + k4 * 4);
            #pragma unroll
            for (int jj = 0; jj < 4; jj++)
                w[jj] = *(const ulonglong2*)(ws_s + (jj * 16 + tx) * XPITCH + k4 * 4);
            #pragma unroll
            for (int ii = 0; ii < 4; ii++)
                #pragma unroll
                for (int jj = 0; jj < 4; jj++) {
                    fma2(acc[ii][jj], a[ii].x, w[jj].x);
                    fma2(acc[ii][jj], a[ii].y, w[jj].y);
                }
        }
        __syncthreads();
    }

    #pragma unroll
    for (int ii = 0; ii < 4; ii++) {
        size_t m = mbase + ty * 4 + ii;
        size_t tt = m >> 8;
        size_t b = m & 255;
        float* op = out + (b * T_STEPS + tt) * IN_DIM;
        #pragma unroll
        for (int jj = 0; jj < 4; jj++) {
            int o = jj * 16 + tx;
            op[o] = redpair(acc[ii][jj]) + b_out[o];
        }
    }
}

extern "C" void kernel_launch(void* const* d_in, const int* in_sizes, int n_in,
                              void* d_out, int out_size)
{
    const float* input  = (const float*)d_in[0];
    const float* hidden = (const float*)d_in[1];
    const float* W_dec  = (const float*)d_in[2];
    const float* b_dec  = (const float*)d_in[3];
    const float* W_ih   = (const float*)d_in[4];
    const float* W_hh   = (const float*)d_in[5];
    const float* b_ih   = (const float*)d_in[6];
    const float* b_hh   = (const float*)d_in[7];
    const float* W_out  = (const float*)d_in[8];
    const float* b_out  = (const float*)d_in[9];
    float* out = (float*)d_out;

    cudaFuncSetAttribute(k_rec, cudaFuncAttributeMaxDynamicSharedMemorySize, SMEM_BYTES);

    k_xprep<<<(T_STEPS * BATCH * 16) / 256, 256>>>(input);
    k_rec<<<GROUPS * JCTAS, 256, SMEM_BYTES>>>(input, hidden, W_dec, b_dec,
                                               W_ih, W_hh, b_ih, b_hh);
    k_out<<<(T_STEPS * BATCH) / 64, 256>>>(W_out, b_out, out);
}

// round 16
// speedup vs baseline: 1.7150x; 1.3380x over previous
#include <cuda_runtime.h>
#include <cuda_bf16.h>
#include <cstdint>

// Problem constants
#define T_STEPS 2048
#define BATCH   256
#define IN_DIM  64
#define HID     256
#define GROUPS  16
#define JCTAS   8
#define ROWS    16

// smem layout (4-byte word offsets)
#define OFF_HHI  0          // h tile hi frags: 16 chunks x 32 lanes x 4 words = 2048
#define OFF_HLO  2048
#define OFF_XHI  4096       // x tile hi: 4 chunks x 32 x 4 = 512
#define OFF_XLO  4608
#define OFF_BLOH 5120       // W_hh lo frags: 8 warps x 3 gates x 8 chunks x 64 = 12288
#define OFF_BLOX 17408      // W_ih lo frags: 8 x 3 x 2 x 64 = 3072
#define OFF_PART 20480      // cross-warp partials: 128 x 20 = 2560
#define SMEM_UNITS 23040
#define SMEM_BYTES (SMEM_UNITS*4)

// Device scratch
__device__ float g_hs[(size_t)T_STEPS * BATCH * HID];          // trajectory [T][B][H]
__device__ unsigned int g_hfrag_hi[2][GROUPS * 2048];          // h state, bf16x2 frag layout
__device__ unsigned int g_hfrag_lo[2][GROUPS * 2048];
__device__ unsigned int g_xfrag_hi[(size_t)T_STEPS * GROUPS * 512];
__device__ unsigned int g_xfrag_lo[(size_t)T_STEPS * GROUPS * 512];
__device__ unsigned int g_arr[GROUPS * 32];                    // per-group arrival counters

typedef unsigned long long ull;

// ---- helpers ----
__device__ __forceinline__ uint32_t packbf2(float f0, float f1) {   // f0 -> low half
    uint32_t r; asm("cvt.rn.bf16x2.f32 %0, %1, %2;" : "=r"(r) : "f"(f1), "f"(f0)); return r;
}
__device__ __forceinline__ float bfhi(float f) {
    return __bfloat162float(__float2bfloat16_rn(f));
}
__device__ __forceinline__ float2 unpackbf2(uint32_t u) {
    __nv_bfloat162 b = *reinterpret_cast<__nv_bfloat162*>(&u);
    return make_float2(__bfloat162float(b.x), __bfloat162float(b.y));
}
__device__ __forceinline__ float fast_sig(float x) {
    return __fdividef(1.f, 1.f + __expf(-x));
}
__device__ __forceinline__ float fast_tanh(float x) {
    float y; asm("tanh.approx.f32 %0, %1;" : "=f"(y) : "f"(x)); return y;
}
__device__ __forceinline__ unsigned int ld_acq(const unsigned int* p) {
    unsigned int v;
    asm volatile("ld.acquire.gpu.global.u32 %0, [%1];" : "=r"(v) : "l"(p));
    return v;
}
__device__ __forceinline__ void red_release(unsigned int* p) {
    asm volatile("red.release.gpu.global.add.u32 [%0], %1;" :: "l"(p), "r"(1u) : "memory");
}
__device__ __forceinline__ uint32_t smem_u32(const void* p) {
    uint32_t a;
    asm("{ .reg .u64 t; cvta.to.shared.u64 t, %1; cvt.u32.u64 %0, t; }" : "=r"(a) : "l"(p));
    return a;
}
__device__ __forceinline__ void cp_async16(uint32_t saddr, const void* gaddr) {
    asm volatile("cp.async.cg.shared.global [%0], [%1], 16;" :: "r"(saddr), "l"(gaddr) : "memory");
}
__device__ __forceinline__ void cp_async_commit_wait() {
    asm volatile("cp.async.commit_group;" ::: "memory");
    asm volatile("cp.async.wait_group 0;" ::: "memory");
}
// packed fp32x2 FMA (k_out)
__device__ __forceinline__ void fma2(ull& acc, ull a, ull b) {
    asm("fma.rn.f32x2 %0, %1, %2, %0;" : "+l"(acc) : "l"(a), "l"(b));
}
__device__ __forceinline__ float redpair(ull v) {
    float lo = __uint_as_float((unsigned int)(v & 0xffffffffULL));
    float hi = __uint_as_float((unsigned int)(v >> 32));
    return lo + hi;
}

// m16n8k16 bf16 mma, D += A*B
#define MMA16(D, A, B0, B1) \
    asm volatile("mma.sync.aligned.m16n8k16.row.col.f32.bf16.bf16.f32 " \
                 "{%0,%1,%2,%3},{%4,%5,%6,%7},{%8,%9},{%0,%1,%2,%3};" \
                 : "+f"(D[0]), "+f"(D[1]), "+f"(D[2]), "+f"(D[3]) \
                 : "r"((A).x), "r"((A).y), "r"((A).z), "r"((A).w), "r"(B0), "r"(B1))

// =====================================================================
// Pre-kernel: xs[t] = (t==0 ? 0 : input[t-1]) -> bf16 hi/lo frag arrays.
// One thread per (t, b, group-of-4-cols).
// =====================================================================
__global__ void __launch_bounds__(256) k_xprep(const float* __restrict__ input)
{
    size_t gid = (size_t)blockIdx.x * 256 + threadIdx.x;   // T*B*16 total
    int i4 = (int)(gid & 15);
    size_t tb = gid >> 4;
    int b = (int)(tb & 255);
    int t = (int)(tb >> 8);
    if (t >= T_STEPS) return;

    float vals[4];
    if (t == 0) {
        vals[0] = vals[1] = vals[2] = vals[3] = 0.f;
    } else {
        float4 v = *(const float4*)(input + (((size_t)(t - 1) * BATCH + b) * IN_DIM) + i4 * 4);
        vals[0] = v.x; vals[1] = v.y; vals[2] = v.z; vals[3] = v.w;
    }
    int grp = b >> 4, r = b & 15;
    size_t base = ((size_t)t * GROUPS + grp) * 512;
    #pragma unroll
    for (int pp = 0; pp < 2; pp++) {
        int p = i4 * 2 + pp;               // col pair index, cols 2p, 2p+1
        float v0 = vals[2 * pp], v1 = vals[2 * pp + 1];
        int chunk = p >> 3;
        int q_l = p & 3;
        int khalf = (p >> 2) & 1;
        size_t idx = base + (size_t)((chunk * 32 + (r & 7) * 4 + q_l) * 4 + (r >> 3) + 2 * khalf);
        g_xfrag_hi[idx] = packbf2(v0, v1);
        g_xfrag_lo[idx] = packbf2(v0 - bfhi(v0), v1 - bfhi(v1));
    }
}

// =====================================================================
// Persistent recurrent kernel: bf16 m16n8k16 mma (3-product split),
// bf16x2 fragment-layout h exchange, R14 counter sync.
// Warp w: col-tile t = w&3 (8 cols), K-half kh = w>>2.
// =====================================================================
__global__ void __launch_bounds__(256, 1) k_rec(
    const float* __restrict__ input,
    const float* __restrict__ hidden,  // [1][B][3]
    const float* __restrict__ W_dec,   // [H][3]
    const float* __restrict__ b_dec,   // [H]
    const float* __restrict__ W_ih,    // [3H][I]
    const float* __restrict__ W_hh,    // [3H][H]
    const float* __restrict__ b_ih,    // [3H]
    const float* __restrict__ b_hh)    // [3H]
{
    extern __shared__ unsigned int smu[];
    float* smf = (float*)smu;
    const uint32_t sbase = smem_u32(smu);

    const int tid = threadIdx.x;
    const int lane = tid & 31;
    const int warp = tid >> 5;
    const int t = warp & 3;           // col tile (8 cols)
    const int kh = warp >> 2;         // K half
    const int grp = blockIdx.x >> 3;
    const int jc = blockIdx.x & 7;
    const int rbase = grp * ROWS;

    unsigned int* my_arr = &g_arr[grp * 32];

    // --- B fragments: hi in registers, lo in smem ---
    uint32_t bh_h[3][8][2];
    uint32_t bh_x[3][2][2];
    {
        const int ncol = jc * 32 + t * 8 + (lane >> 2);
        const int q = lane & 3;
        #pragma unroll
        for (int g = 0; g < 3; g++) {
            #pragma unroll
            for (int cc = 0; cc < 8; cc++) {
                const float* wr = W_hh + (size_t)(g * HID + ncol) * HID + kh * 128 + cc * 16 + 2 * q;
                float w0 = wr[0], w1 = wr[1], w2 = wr[8], w3 = wr[9];
                bh_h[g][cc][0] = packbf2(w0, w1);
                bh_h[g][cc][1] = packbf2(w2, w3);
                int bi = OFF_BLOH + (((warp * 3 + g) * 8 + cc) * 64 + lane * 2);
                smu[bi]     = packbf2(w0 - bfhi(w0), w1 - bfhi(w1));
                smu[bi + 1] = packbf2(w2 - bfhi(w2), w3 - bfhi(w3));
            }
            #pragma unroll
            for (int cc = 0; cc < 2; cc++) {
                const float* wr = W_ih + (size_t)(g * HID + ncol) * IN_DIM + kh * 32 + cc * 16 + 2 * q;
                float w0 = wr[0], w1 = wr[1], w2 = wr[8], w3 = wr[9];
                bh_x[g][cc][0] = packbf2(w0, w1);
                bh_x[g][cc][1] = packbf2(w2, w3);
                int bi = OFF_BLOX + (((warp * 3 + g) * 2 + cc) * 64 + lane * 2);
                smu[bi]     = packbf2(w0 - bfhi(w0), w1 - bfhi(w1));
                smu[bi + 1] = packbf2(w2 - bfhi(w2), w3 - bfhi(w3));
            }
        }
    }

    // gate-phase constants (meaningful for warps 0-3)
    const int grow = lane >> 2;                 // local row 0..7 (and +8)
    const int q = lane & 3;
    const int colg = jc * 32 + t * 8 + 2 * q;   // global col of D c0/c2
    const float bs_r0 = b_ih[colg]             + b_hh[colg];
    const float bs_r1 = b_ih[colg + 1]         + b_hh[colg + 1];
    const float bs_z0 = b_ih[HID + colg]       + b_hh[HID + colg];
    const float bs_z1 = b_ih[HID + colg + 1]   + b_hh[HID + colg + 1];
    const float bxn0  = b_ih[2 * HID + colg];
    const float bxn1  = b_ih[2 * HID + colg + 1];
    const float bhn0  = b_hh[2 * HID + colg];
    const float bhn1  = b_hh[2 * HID + colg + 1];
    // frag word index of owned h positions: word = row grow, word+1 = row grow+8
    const int hch = jc * 2 + (t >> 1);
    const int hidx = (hch * 32 + grow * 4 + q) * 4 + 2 * (t & 1);

    // --- h0 -> g_hfrag[0]: one col-pair per thread (16 rows x 16 pairs) ---
    {
        int r = tid >> 4, cp = tid & 15;
        int cg = jc * 32 + cp * 2;
        int b = rbase + r;
        float h0v = hidden[b * 3 + 0], h1v = hidden[b * 3 + 1], h2v = hidden[b * 3 + 2];
        float v0 = b_dec[cg]     + h0v * W_dec[cg * 3]       + h1v * W_dec[cg * 3 + 1]       + h2v * W_dec[cg * 3 + 2];
        float v1 = b_dec[cg + 1] + h0v * W_dec[(cg + 1) * 3] + h1v * W_dec[(cg + 1) * 3 + 1] + h2v * W_dec[(cg + 1) * 3 + 2];
        int chunk = jc * 2 + (cp >> 3);
        int q_l = cp & 3;
        int khalf = (cp >> 2) & 1;
        int idx = grp * 2048 + (chunk * 32 + (r & 7) * 4 + q_l) * 4 + (r >> 3) + 2 * khalf;
        g_hfrag_hi[0][idx] = packbf2(v0, v1);
        g_hfrag_lo[0][idx] = packbf2(v0 - bfhi(v0), v1 - bfhi(v1));
    }
    __syncthreads();
    if (warp < 4 && lane == 0) red_release(my_arr);   // 4/CTA -> 32/group

    // ---------------- time-step loop ----------------
    for (int s = 0; s < T_STEPS; s++) {
        const int buf = s & 1;
        // wait h(s)
        if (lane == 0) {
            unsigned int tgt = 32u * (unsigned int)(s + 1);
            while (ld_acq(my_arr) < tgt) { }
        }
        __syncwarp();

        // stage h (hi+lo, 16KB) + x (hi+lo, 4KB), frag layout verbatim
        {
            const uint4* shi = (const uint4*)(g_hfrag_hi[buf] + grp * 2048);   // 512 uint4
            const uint4* slo = (const uint4*)(g_hfrag_lo[buf] + grp * 2048);
            #pragma unroll
            for (int it = 0; it < 2; it++) {
                int ci = tid + it * 256;
                cp_async16(sbase + (OFF_HHI + ci * 4) * 4, shi + ci);
                cp_async16(sbase + (OFF_HLO + ci * 4) * 4, slo + ci);
            }
            if (tid < 128) {
                const uint4* xhi = (const uint4*)(g_xfrag_hi + ((size_t)s * GROUPS + grp) * 512);
                cp_async16(sbase + (OFF_XHI + tid * 4) * 4, xhi + tid);
            } else {
                const uint4* xlo = (const uint4*)(g_xfrag_lo + ((size_t)s * GROUPS + grp) * 512);
                cp_async16(sbase + (OFF_XLO + (tid - 128) * 4) * 4, xlo + (tid - 128));
            }
        }
        cp_async_commit_wait();
        __syncthreads();

        // --- mma: 3-product bf16 chains into 4 D fragments ---
        float dr[4] = {0.f, 0.f, 0.f, 0.f};
        float dz[4] = {0.f, 0.f, 0.f, 0.f};
        float dnh[4] = {0.f, 0.f, 0.f, 0.f};
        float dnx[4] = {0.f, 0.f, 0.f, 0.f};

        const uint4* Ahh = (const uint4*)(smu + OFF_HHI);
        const uint4* Ahl = (const uint4*)(smu + OFF_HLO);
        #pragma unroll
        for (int cc = 0; cc < 8; cc++) {
            int ai = (kh * 8 + cc) * 32 + lane;
            uint4 ah = Ahh[ai];
            uint4 al = Ahl[ai];
            {
                uint2 bl = *(const uint2*)(smu + OFF_BLOH + (((warp * 3 + 0) * 8 + cc) * 64 + lane * 2));
                MMA16(dr, ah, bh_h[0][cc][0], bh_h[0][cc][1]);
                MMA16(dr, al, bh_h[0][cc][0], bh_h[0][cc][1]);
                MMA16(dr, ah, bl.x, bl.y);
            }
            {
                uint2 bl = *(const uint2*)(smu + OFF_BLOH + (((warp * 3 + 1) * 8 + cc) * 64 + lane * 2));
                MMA16(dz, ah, bh_h[1][cc][0], bh_h[1][cc][1]);
                MMA16(dz, al, bh_h[1][cc][0], bh_h[1][cc][1]);
                MMA16(dz, ah, bl.x, bl.y);
            }
            {
                uint2 bl = *(const uint2*)(smu + OFF_BLOH + (((warp * 3 + 2) * 8 + cc) * 64 + lane * 2));
                MMA16(dnh, ah, bh_h[2][cc][0], bh_h[2][cc][1]);
                MMA16(dnh, al, bh_h[2][cc][0], bh_h[2][cc][1]);
                MMA16(dnh, ah, bl.x, bl.y);
            }
        }
        const uint4* Axh = (const uint4*)(smu + OFF_XHI);
        const uint4* Axl = (const uint4*)(smu + OFF_XLO);
        #pragma unroll
        for (int cc = 0; cc < 2; cc++) {
            int ai = (kh * 2 + cc) * 32 + lane;
            uint4 ah = Axh[ai];
            uint4 al = Axl[ai];
            {
                uint2 bl = *(const uint2*)(smu + OFF_BLOX + (((warp * 3 + 0) * 2 + cc) * 64 + lane * 2));
                MMA16(dr, ah, bh_x[0][cc][0], bh_x[0][cc][1]);
                MMA16(dr, al, bh_x[0][cc][0], bh_x[0][cc][1]);
                MMA16(dr, ah, bl.x, bl.y);
            }
            {
                uint2 bl = *(const uint2*)(smu + OFF_BLOX + (((warp * 3 + 1) * 2 + cc) * 64 + lane * 2));
                MMA16(dz, ah, bh_x[1][cc][0], bh_x[1][cc][1]);
                MMA16(dz, al, bh_x[1][cc][0], bh_x[1][cc][1]);
                MMA16(dz, ah, bl.x, bl.y);
            }
            {
                uint2 bl = *(const uint2*)(smu + OFF_BLOX + (((warp * 3 + 2) * 2 + cc) * 64 + lane * 2));
                MMA16(dnx, ah, bh_x[2][cc][0], bh_x[2][cc][1]);
                MMA16(dnx, al, bh_x[2][cc][0], bh_x[2][cc][1]);
                MMA16(dnx, ah, bl.x, bl.y);
            }
        }

        // --- cross-K-half reduction: warps 4-7 export partials ---
        if (warp >= 4) {
            float* pp = smf + OFF_PART + ((warp - 4) * 32 + lane) * 20;
            *(float4*)(pp)      = make_float4(dr[0], dr[1], dr[2], dr[3]);
            *(float4*)(pp + 4)  = make_float4(dz[0], dz[1], dz[2], dz[3]);
            *(float4*)(pp + 8)  = make_float4(dnh[0], dnh[1], dnh[2], dnh[3]);
            *(float4*)(pp + 12) = make_float4(dnx[0], dnx[1], dnx[2], dnx[3]);
        }
        __syncthreads();

        if (warp < 4) {
            const float* pp = smf + OFF_PART + (warp * 32 + lane) * 20;
            float4 pr = *(const float4*)(pp);
            float4 pz = *(const float4*)(pp + 4);
            float4 pn = *(const float4*)(pp + 8);
            float4 px = *(const float4*)(pp + 12);
            dr[0] += pr.x; dr[1] += pr.y; dr[2] += pr.z; dr[3] += pr.w;
            dz[0] += pz.x; dz[1] += pz.y; dz[2] += pz.z; dz[3] += pz.w;
            dnh[0] += pn.x; dnh[1] += pn.y; dnh[2] += pn.z; dnh[3] += pn.w;
            dnx[0] += px.x; dnx[1] += px.y; dnx[2] += px.z; dnx[3] += px.w;

            // h_old (4 positions) from staged frag tiles
            uint2 uh = *(const uint2*)(smu + OFF_HHI + hidx);
            uint2 ul = *(const uint2*)(smu + OFF_HLO + hidx);
            float2 h0p = unpackbf2(uh.x), h8p = unpackbf2(uh.y);
            float2 l0p = unpackbf2(ul.x), l8p = unpackbf2(ul.y);
            float hold00 = h0p.x + l0p.x;   // (grow,   colg)
            float hold01 = h0p.y + l0p.y;   // (grow,   colg+1)
            float hold10 = h8p.x + l8p.x;   // (grow+8, colg)
            float hold11 = h8p.y + l8p.y;   // (grow+8, colg+1)

            // gates: c0=(grow,colg), c1=(grow,colg+1), c2=(grow+8,colg), c3=(grow+8,colg+1)
            float rg, zg, ng;
            rg = fast_sig(dr[0] + bs_r0); zg = fast_sig(dz[0] + bs_z0);
            ng = fast_tanh(dnx[0] + bxn0 + rg * (dnh[0] + bhn0));
            float hn00 = zg * (hold00 - ng) + ng;
            rg = fast_sig(dr[1] + bs_r1); zg = fast_sig(dz[1] + bs_z1);
            ng = fast_tanh(dnx[1] + bxn1 + rg * (dnh[1] + bhn1));
            float hn01 = zg * (hold01 - ng) + ng;
            rg = fast_sig(dr[2] + bs_r0); zg = fast_sig(dz[2] + bs_z0);
            ng = fast_tanh(dnx[2] + bxn0 + rg * (dnh[2] + bhn0));
            float hn10 = zg * (hold10 - ng) + ng;
            rg = fast_sig(dr[3] + bs_r1); zg = fast_sig(dz[3] + bs_z1);
            ng = fast_tanh(dnx[3] + bxn1 + rg * (dnh[3] + bhn1));
            float hn11 = zg * (hold11 - ng) + ng;

            // h_new -> frag arrays (hi/lo) for next step
            unsigned int* dhi = g_hfrag_hi[buf ^ 1] + grp * 2048;
            unsigned int* dlo = g_hfrag_lo[buf ^ 1] + grp * 2048;
            *(uint2*)(dhi + hidx) = make_uint2(packbf2(hn00, hn01), packbf2(hn10, hn11));
            *(uint2*)(dlo + hidx) = make_uint2(
                packbf2(hn00 - bfhi(hn00), hn01 - bfhi(hn01)),
                packbf2(hn10 - bfhi(hn10), hn11 - bfhi(hn11)));

            __syncwarp();
            if (lane == 0) red_release(my_arr);

            // trajectory (off critical path)
            float* hd = g_hs + ((size_t)s * BATCH + rbase + grow) * HID + colg;
            *(float2*)hd = make_float2(hn00, hn01);
            *(float2*)(hd + 8 * HID) = make_float2(hn10, hn11);
        }
    }

    // counter reset for next graph replay
    if (jc == 0 && tid == 0) {
        unsigned int fin = 32u * (unsigned int)(T_STEPS + 1);
        while (ld_acq(my_arr) < fin) { }
        *my_arr = 0u;
        __threadfence();
    }
}

// =====================================================================
// Output GEMM (proven R3 version): 64 rows x 64 o, K=256 in 4 chunks
// =====================================================================
#define XPITCH 68
__global__ void __launch_bounds__(256) k_out(
    const float* __restrict__ W_out,   // [I][H]
    const float* __restrict__ b_out,   // [I]
    float* __restrict__ out)           // [B][T][I]
{
    __shared__ float hs_s[64 * XPITCH];
    __shared__ float ws_s[64 * XPITCH];
    const int tid = threadIdx.x;
    const int tx = tid & 15, ty = tid >> 4;
    const size_t mbase = (size_t)blockIdx.x * 64;

    ull acc[4][4];
    #pragma unroll
    for (int ii = 0; ii < 4; ii++)
        #pragma unroll
        for (int jj = 0; jj < 4; jj++) acc[ii][jj] = 0ULL;

    for (int kc = 0; kc < 4; kc++) {
        const int kofs = kc * 64;
        for (int i = tid; i < 1024; i += 256) {
            int row = i >> 4, c = i & 15;
            float4 v = *(const float4*)(g_hs + (mbase + row) * HID + kofs + c * 4);
            *(float4*)(hs_s + row * XPITCH + c * 4) = v;
        }
        for (int i = tid; i < 1024; i += 256) {
            int row = i >> 4, c = i & 15;
            float4 v = *(const float4*)(W_out + (size_t)row * HID + kofs + c * 4);
            *(float4*)(ws_s + row * XPITCH + c * 4) = v;
        }
        __syncthreads();
        #pragma unroll
        for (int k4 = 0; k4 < 16; k4++) {
            ulonglong2 a[4], w[4];
            #pragma unroll
            for (int ii = 0; ii < 4; ii++)
                a[ii] = *(const ulonglong2*)(hs_s + (ty * 4 + ii) * XPITCH + k4 * 4);
            #pragma unroll
            for (int jj = 0; jj < 4; jj++)
                w[jj] = *(const ulonglong2*)(ws_s + (jj * 16 + tx) * XPITCH + k4 * 4);
            #pragma unroll
            for (int ii = 0; ii < 4; ii++)
                #pragma unroll
                for (int jj = 0; jj < 4; jj++) {
                    fma2(acc[ii][jj], a[ii].x, w[jj].x);
                    fma2(acc[ii][jj], a[ii].y, w[jj].y);
                }
        }
        __syncthreads();
    }

    #pragma unroll
    for (int ii = 0; ii < 4; ii++) {
        size_t m = mbase + ty * 4 + ii;
        size_t tt = m >> 8;
        size_t b = m & 255;
        float* op = out + (b * T_STEPS + tt) * IN_DIM;
        #pragma unroll
        for (int jj = 0; jj < 4; jj++) {
            int o = jj * 16 + tx;
            op[o] = redpair(acc[ii][jj]) + b_out[o];
        }
    }
}

extern "C" void kernel_launch(void* const* d_in, const int* in_sizes, int n_in,
                              void* d_out, int out_size)
{
    const float* input  = (const float*)d_in[0];
    const float* hidden = (const float*)d_in[1];
    const float* W_dec  = (const float*)d_in[2];
    const float* b_dec  = (const float*)d_in[3];
    const float* W_ih   = (const float*)d_in[4];
    const float* W_hh   = (const float*)d_in[5];
    const float* b_ih   = (const float*)d_in[6];
    const float* b_hh   = (const float*)d_in[7];
    const float* W_out  = (const float*)d_in[8];
    const float* b_out  = (const float*)d_in[9];
    float* out = (float*)d_out;

    cudaFuncSetAttribute(k_rec, cudaFuncAttributeMaxDynamicSharedMemorySize, SMEM_BYTES);

    k_xprep<<<(T_STEPS * BATCH * 16) / 256, 256>>>(input);
    k_rec<<<GROUPS * JCTAS, 256, SMEM_BYTES>>>(input, hidden, W_dec, b_dec,
                                               W_ih, W_hh, b_ih, b_hh);
    k_out<<<(T_STEPS * BATCH) / 64, 256>>>(W_out, b_out, out);
}